// round 1
// baseline (speedup 1.0000x reference)
#include <cuda_runtime.h>

// ---------------------------------------------------------------------------
// Photonic FFN block: per row (64 features) simulate a 6-mode cutoff-2 Fock
// circuit, probs = |amp|^2, y = probs + x, LayerNorm(y).
// One thread = one sample. State (64 complex amps) lives in registers.
// Wire w bit = 1 << (5 - w)   (wire 0 is most significant, matching reshape).
// ---------------------------------------------------------------------------

static __device__ __forceinline__ void cmul_inplace(float& r, float& i, float br, float bi) {
    float ar = r, ai = i;
    r = ar * br - ai * bi;
    i = ar * bi + ai * br;
}

// diag gate: bit==0 amps *= d0 (real), bit==1 amps *= (c1r + i c1i)
template <int BIT>
static __device__ __forceinline__ void g_diag_mixed(float* sr, float* si,
                                                    float d0, float c1r, float c1i) {
#pragma unroll
    for (int i = 0; i < 64; ++i) {
        if (i & BIT) {
            cmul_inplace(sr[i], si[i], c1r, c1i);
        } else {
            sr[i] *= d0;
            si[i] *= d0;
        }
    }
}

// rotation: bit==1 amps *= (cr + i ci)
template <int BIT>
static __device__ __forceinline__ void g_rot(float* sr, float* si, float cr, float ci) {
#pragma unroll
    for (int i = 0; i < 64; ++i) {
        if (i & BIT) cmul_inplace(sr[i], si[i], cr, ci);
    }
}

// real 2x2 gate (layer displacement, phi = 0): all-real matrix entries
template <int BIT>
static __device__ __forceinline__ void g_disp_real(float* sr, float* si,
                                                   float m00, float m01, float m10, float m11) {
#pragma unroll
    for (int i = 0; i < 64; ++i) {
        if (!(i & BIT)) {
            const int j = i | BIT;
            float a0r = sr[i], a0i = si[i];
            float a1r = sr[j], a1i = si[j];
            sr[i] = m00 * a0r + m01 * a1r;
            si[i] = m00 * a0i + m01 * a1i;
            sr[j] = m10 * a0r + m11 * a1r;
            si[j] = m10 * a0i + m11 * a1i;
        }
    }
}

// beamsplitter on wires with bits BA (mode a) and BB (mode b):
//  |01> -> c|01> + beta|10> ;  |10> -> -conj(beta)|01> + c|10> ;  |11> *= c2
template <int BA, int BB>
static __device__ __forceinline__ void g_bs(float* sr, float* si,
                                            float c, float br, float bi, float c2) {
#pragma unroll
    for (int i = 0; i < 64; ++i) {
        if ((i & (BA | BB)) == 0) {
            const int i01 = i | BB;
            const int i10 = i | BA;
            const int i11 = i | BA | BB;
            float xr = sr[i01], xi = si[i01];
            float yr = sr[i10], yi = si[i10];
            sr[i01] = c * xr + br * yr - bi * yi;
            si[i01] = c * xi + br * yi + bi * yr;
            sr[i10] = c * yr - br * xr - bi * xi;
            si[i10] = c * yi - br * xi + bi * xr;
            sr[i11] *= c2;
            si[i11] *= c2;
        }
    }
}

#define V(k) __ldg(v + (k))

#define BS_CALL(BA, BB, TH, PH)                                        \
    do {                                                               \
        float th_ = (TH), ph_ = (PH);                                  \
        float s_, c_, sp_, cp_;                                        \
        __sincosf(th_, &s_, &c_);                                      \
        __sincosf(ph_, &sp_, &cp_);                                    \
        g_bs<BA, BB>(sr, si, c_, s_ * cp_, s_ * sp_, c_ * c_ - s_ * s_); \
    } while (0)

// fused rot(phi) then squeeze(r): d0 = sech^0.5 (real), d1 = sech^1.5 * e^{i phi}
#define DIAG_CALL(BIT, PH, RR)                                         \
    do {                                                               \
        float r_ = (RR);                                               \
        float e_ = __expf(r_);                                         \
        float ch_ = 0.5f * (e_ + __fdividef(1.0f, e_));                \
        float d0_ = rsqrtf(ch_);                                       \
        float d1_ = d0_ * __fdividef(1.0f, ch_);                       \
        float sn_, cs_;                                                \
        __sincosf((PH), &sn_, &cs_);                                   \
        g_diag_mixed<BIT>(sr, si, d0_, d1_ * cs_, d1_ * sn_);          \
    } while (0)

// rot(phi) then real displacement D(r, 0)
#define ROTDISP_CALL(BIT, PH, RD)                                      \
    do {                                                               \
        float sn_, cs_;                                                \
        __sincosf((PH), &sn_, &cs_);                                   \
        g_rot<BIT>(sr, si, cs_, sn_);                                  \
        float r_ = (RD);                                               \
        float p_ = __expf(-0.5f * r_ * r_);                            \
        g_disp_real<BIT>(sr, si, p_, -p_ * r_, p_ * r_, p_ * (1.0f - r_ * r_)); \
    } while (0)

#define ROT_CALL(BIT, PH)                                              \
    do {                                                               \
        float sn_, cs_;                                                \
        __sincosf((PH), &sn_, &cs_);                                   \
        g_rot<BIT>(sr, si, cs_, sn_);                                  \
    } while (0)

__global__ void __launch_bounds__(128)
ffb_kernel(const float* __restrict__ x, const float* __restrict__ var,
           const float* __restrict__ gamma, const float* __restrict__ beta,
           float* __restrict__ out, int nrows) {
    int t = blockIdx.x * blockDim.x + threadIdx.x;
    if (t >= nrows) return;
    const float* xr = x + (long long)t * 64;

    float sr[64], si[64];

    // ---------------- Encoding collapses to a product state -----------------
    // state = prod_w ⊗ (A_w, B_w):
    //   A_w    = sqrt(sech x[2w]) * exp(-rd^2/2) * sqrt(sech r2)          (real)
    //   |B_w|  = A_w-prefactors * rd * sech(r2)^1.5
    //   arg B_w= phid + kerr + rot
    // (encoding BS + first rot act trivially on |0...0>.)
    {
        float Ar[6], Brr[6], Bri[6];
#pragma unroll
        for (int w = 0; w < 6; ++w) {
            float r1 = __ldg(xr + 2 * w);
            float e1 = __expf(r1);
            float ch1 = 0.5f * (e1 + __fdividef(1.0f, e1));
            float cw = rsqrtf(ch1);  // sqrt(sech r1)

            float rd   = __ldg(xr + 28 + 2 * w);
            float phid = __ldg(xr + 29 + 2 * w);
            float pref = __expf(-0.5f * rd * rd);

            float kk = __ldg(xr + 40 + w);

            float r2 = __ldg(xr + 46 + 2 * w);
            float e2 = __expf(r2);
            float ch2 = 0.5f * (e2 + __fdividef(1.0f, e2));
            float s0 = rsqrtf(ch2);                       // sech^0.5
            float s1 = s0 * __fdividef(1.0f, ch2);        // sech^1.5

            float phr = __ldg(xr + 58 + w);
            float ang = phid + kk + phr;
            float sn, cs;
            __sincosf(ang, &sn, &cs);

            float base = cw * pref;
            Ar[w] = base * s0;
            float bm = base * rd * s1;
            Brr[w] = bm * cs;
            Bri[w] = bm * sn;
        }
        // outer product, building from wire 5 (LSB) up to wire 0 (MSB)
        sr[0] = Ar[5]; si[0] = 0.0f;
        sr[1] = Brr[5]; si[1] = Bri[5];
#pragma unroll
        for (int w = 4; w >= 0; --w) {
            const int len = 1 << (5 - w);
#pragma unroll
            for (int j = 0; j < 32; ++j) {
                if (j < len) {
                    float ar = sr[j], ai = si[j];
                    sr[len + j] = Brr[w] * ar - Bri[w] * ai;
                    si[len + j] = Brr[w] * ai + Bri[w] * ar;
                    sr[j] = Ar[w] * ar;
                    si[j] = Ar[w] * ai;
                }
            }
        }
    }

    // ---------------- Variational layers ------------------------------------
#pragma unroll 1
    for (int l = 0; l < 2; ++l) {
        const float* v = var + l * 50;

        // BS chain 1 (v[0:10])
        BS_CALL(32, 16, V(0), V(1));
        BS_CALL(16, 8, V(2), V(3));
        BS_CALL(8, 4, V(4), V(5));
        BS_CALL(4, 2, V(6), V(7));
        BS_CALL(2, 1, V(8), V(9));

        // rot (v[10:16]) fused with squeeze (v[16:22])
        DIAG_CALL(32, V(10), V(16));
        DIAG_CALL(16, V(11), V(17));
        DIAG_CALL(8, V(12), V(18));
        DIAG_CALL(4, V(13), V(19));
        DIAG_CALL(2, V(14), V(20));
        DIAG_CALL(1, V(15), V(21));

        // BS chain 2 (v[22:32])
        BS_CALL(32, 16, V(22), V(23));
        BS_CALL(16, 8, V(24), V(25));
        BS_CALL(8, 4, V(26), V(27));
        BS_CALL(4, 2, V(28), V(29));
        BS_CALL(2, 1, V(30), V(31));

        // rot (v[32:38]) + real displacement (v[38:44], phi = 0)
        ROTDISP_CALL(32, V(32), V(38));
        ROTDISP_CALL(16, V(33), V(39));
        ROTDISP_CALL(8, V(34), V(40));
        ROTDISP_CALL(4, V(35), V(41));
        ROTDISP_CALL(2, V(36), V(42));
        ROTDISP_CALL(1, V(37), V(43));

        // Kerr rotations (v[44:50]) — pure phases: skip on the LAST layer
        // (|amp|^2 is invariant), must apply on layer 0 (BS mixes phases).
        if (l == 0) {
            ROT_CALL(32, V(44));
            ROT_CALL(16, V(45));
            ROT_CALL(8, V(46));
            ROT_CALL(4, V(47));
            ROT_CALL(2, V(48));
            ROT_CALL(1, V(49));
        }
    }

    // ---------------- probs + residual + LayerNorm ---------------------------
    float mean = 0.0f;
#pragma unroll
    for (int i = 0; i < 64; ++i) {
        float p = sr[i] * sr[i] + si[i] * si[i];
        float y = p + __ldg(xr + i);
        sr[i] = y;
        mean += y;
    }
    mean *= 0.015625f;
    float var2 = 0.0f;
#pragma unroll
    for (int i = 0; i < 64; ++i) {
        float d = sr[i] - mean;
        var2 += d * d;
    }
    var2 *= 0.015625f;
    float inv = rsqrtf(var2 + 1e-5f);

    float* o = out + (long long)t * 64;
#pragma unroll
    for (int i = 0; i < 64; ++i) {
        o[i] = (sr[i] - mean) * inv * __ldg(gamma + i) + __ldg(beta + i);
    }
}

extern "C" void kernel_launch(void* const* d_in, const int* in_sizes, int n_in,
                              void* d_out, int out_size) {
    const float* x     = (const float*)d_in[0];
    const float* var   = (const float*)d_in[1];
    const float* gamma = (const float*)d_in[2];
    const float* beta  = (const float*)d_in[3];
    float* out = (float*)d_out;

    int nrows = in_sizes[0] / 64;  // 131072
    const int threads = 128;
    int blocks = (nrows + threads - 1) / threads;
    ffb_kernel<<<blocks, threads>>>(x, var, gamma, beta, out, nrows);
}

// round 3
// speedup vs baseline: 3.0167x; 3.0167x over previous
#include <cuda_runtime.h>
#include <string.h>

// ---------------------------------------------------------------------------
// Photonic FFN: 6-mode cutoff-2 Fock circuit per row, probs=|amp|^2, +x, LN.
// One thread = one sample. State: 64 complex amps packed as float2 pairs
// along the wire-5 bit (amp index a = 2p + lane). Gates on wires 0..4 are
// purely elementwise on packed regs -> fma.rn.f32x2 (2x FMA-pipe density).
// Global I/O staged through shared memory for full coalescing.
// ---------------------------------------------------------------------------

typedef unsigned long long u64;

static __device__ __forceinline__ float2 f2(float a, float b) { return make_float2(a, b); }
static __device__ __forceinline__ float2 bc(float a) { return make_float2(a, a); }

static __device__ __forceinline__ float2 fma2(float2 a, float2 b, float2 c) {
    u64 ua, ub, uc, ud;
    memcpy(&ua, &a, 8); memcpy(&ub, &b, 8); memcpy(&uc, &c, 8);
    asm("fma.rn.f32x2 %0, %1, %2, %3;" : "=l"(ud) : "l"(ua), "l"(ub), "l"(uc));
    float2 d; memcpy(&d, &ud, 8); return d;
}
static __device__ __forceinline__ float2 mul2(float2 a, float2 b) {
    u64 ua, ub, ud;
    memcpy(&ua, &a, 8); memcpy(&ub, &b, 8);
    asm("mul.rn.f32x2 %0, %1, %2;" : "=l"(ud) : "l"(ua), "l"(ub));
    float2 d; memcpy(&d, &ud, 8); return d;
}
static __device__ __forceinline__ float2 add2(float2 a, float2 b) {
    u64 ua, ub, ud;
    memcpy(&ua, &a, 8); memcpy(&ub, &b, 8);
    asm("add.rn.f32x2 %0, %1, %2;" : "=l"(ud) : "l"(ua), "l"(ub));
    float2 d; memcpy(&d, &ud, 8); return d;
}

// ---- packed gates (p-space: 32 float2 reals R, 32 float2 imags I) ----------

// rotation on wire bit PBIT (amp bit = 2*PBIT): amps with bit set *= (cr + i ci)
template <int PBIT>
static __device__ __forceinline__ void rot_p(float2* R, float2* I, float cr, float ci) {
    const float2 vcr = bc(cr), vci = bc(ci), vnci = bc(-ci);
#pragma unroll
    for (int p = 0; p < 32; ++p) {
        if (p & PBIT) {
            float2 r = R[p], i = I[p];
            R[p] = fma2(i, vnci, mul2(r, vcr));
            I[p] = fma2(i, vcr, mul2(r, vci));
        }
    }
}

// rotation on wire 5 (amp bit 1 = lane): scalar on .y components
static __device__ __forceinline__ void rot_l(float2* R, float2* I, float cr, float ci) {
#pragma unroll
    for (int p = 0; p < 32; ++p) {
        float r = R[p].y, i = I[p].y;
        R[p].y = r * cr - i * ci;
        I[p].y = r * ci + i * cr;
    }
}

// diag (fused rot+squeeze): clear amps *= d0 (real), set amps *= (c1r + i c1i)
template <int PBIT>
static __device__ __forceinline__ void diag_p(float2* R, float2* I,
                                              float d0, float c1r, float c1i) {
    const float2 vd0 = bc(d0), vcr = bc(c1r), vci = bc(c1i), vnci = bc(-c1i);
#pragma unroll
    for (int p = 0; p < 32; ++p) {
        float2 r = R[p], i = I[p];
        if (p & PBIT) {
            R[p] = fma2(i, vnci, mul2(r, vcr));
            I[p] = fma2(i, vcr, mul2(r, vci));
        } else {
            R[p] = mul2(r, vd0);
            I[p] = mul2(i, vd0);
        }
    }
}

// diag on wire 5: mixed constant vector, fully elementwise
static __device__ __forceinline__ void diag_l(float2* R, float2* I,
                                              float d0, float c1r, float c1i) {
    const float2 va = f2(d0, c1r), vb = f2(0.0f, c1i), vnb = f2(0.0f, -c1i);
#pragma unroll
    for (int p = 0; p < 32; ++p) {
        float2 r = R[p], i = I[p];
        R[p] = fma2(i, vnb, mul2(r, va));
        I[p] = fma2(i, va, mul2(r, vb));
    }
}

// real 2x2 displacement on wire bit PBIT (amp bit = 2*PBIT)
template <int PBIT>
static __device__ __forceinline__ void disp_p(float2* R, float2* I,
                                              float m00, float m01, float m10, float m11) {
    const float2 v00 = bc(m00), v01 = bc(m01), v10 = bc(m10), v11 = bc(m11);
#pragma unroll
    for (int p = 0; p < 32; ++p) {
        if (!(p & PBIT)) {
            const int q = p | PBIT;
            float2 r0 = R[p], r1 = R[q], i0 = I[p], i1 = I[q];
            R[p] = fma2(r1, v01, mul2(r0, v00));
            R[q] = fma2(r1, v11, mul2(r0, v10));
            I[p] = fma2(i1, v01, mul2(i0, v00));
            I[q] = fma2(i1, v11, mul2(i0, v10));
        }
    }
}

// real 2x2 displacement on wire 5: within-pair (scalar components)
static __device__ __forceinline__ void disp_l(float2* R, float2* I,
                                              float m00, float m01, float m10, float m11) {
#pragma unroll
    for (int p = 0; p < 32; ++p) {
        float re = R[p].x, ro = R[p].y, ie = I[p].x, io = I[p].y;
        R[p].x = m00 * re + m01 * ro;
        R[p].y = m10 * re + m11 * ro;
        I[p].x = m00 * ie + m01 * io;
        I[p].y = m10 * ie + m11 * io;
    }
}

// beamsplitter, both wire bits >= wire4 (amp bits >= 2): pure packed
template <int PA, int PB>
static __device__ __forceinline__ void bs_p(float2* R, float2* I,
                                            float c, float br, float bi, float c2) {
    const float2 vc = bc(c), vbr = bc(br), vbi = bc(bi);
    const float2 vnbr = bc(-br), vnbi = bc(-bi), vc2 = bc(c2);
#pragma unroll
    for (int p = 0; p < 32; ++p) {
        if ((p & (PA | PB)) == 0) {
            const int p01 = p | PB, p10 = p | PA, p11 = p | PA | PB;
            float2 xr = R[p01], xi = I[p01], yr = R[p10], yi = I[p10];
            R[p01] = fma2(yi, vnbi, fma2(yr, vbr, mul2(xr, vc)));
            I[p01] = fma2(yr, vbi, fma2(yi, vbr, mul2(xi, vc)));
            R[p10] = fma2(xi, vnbi, fma2(xr, vnbr, mul2(yr, vc)));
            I[p10] = fma2(xr, vbi, fma2(xi, vnbr, mul2(yi, vc)));
            R[p11] = mul2(R[p11], vc2);
            I[p11] = mul2(I[p11], vc2);
        }
    }
}

// beamsplitter on wires (4,5) = amp bits (2,1): lane-mixing, scalar components
static __device__ __forceinline__ void bs_m(float2* R, float2* I,
                                            float c, float br, float bi, float c2) {
#pragma unroll
    for (int p = 0; p < 32; p += 2) {
        float xr = R[p].y, xi = I[p].y, yr = R[p + 1].x, yi = I[p + 1].x;
        R[p].y = c * xr + br * yr - bi * yi;
        I[p].y = c * xi + br * yi + bi * yr;
        R[p + 1].x = c * yr - br * xr - bi * xi;
        I[p + 1].x = c * yi - br * xi + bi * xr;
        R[p + 1].y *= c2;
        I[p + 1].y *= c2;
    }
}

#define V(k) __ldg(v + (k))

#define BS_COEF(TH, PH, BODY)                                          \
    do {                                                               \
        float s_, c_, sp_, cp_;                                        \
        __sincosf((TH), &s_, &c_);                                     \
        __sincosf((PH), &sp_, &cp_);                                   \
        float br_ = s_ * cp_, bi_ = s_ * sp_, c2_ = c_ * c_ - s_ * s_; \
        BODY;                                                          \
    } while (0)

#define BS_P(PA, PB, TH, PH) BS_COEF(TH, PH, (bs_p<PA, PB>(Rr, Ri, c_, br_, bi_, c2_)))
#define BS_M(TH, PH) BS_COEF(TH, PH, (bs_m(Rr, Ri, c_, br_, bi_, c2_)))

#define DIAG_COEF(PH, RR, BODY)                                        \
    do {                                                               \
        float r_ = (RR);                                               \
        float e_ = __expf(r_);                                         \
        float ch_ = 0.5f * (e_ + __fdividef(1.0f, e_));                \
        float d0_ = rsqrtf(ch_);                                       \
        float d1_ = d0_ * __fdividef(1.0f, ch_);                       \
        float sn_, cs_;                                                \
        __sincosf((PH), &sn_, &cs_);                                   \
        float c1r_ = d1_ * cs_, c1i_ = d1_ * sn_;                      \
        BODY;                                                          \
    } while (0)

#define DIAG_P(PBIT, PH, RR) DIAG_COEF(PH, RR, (diag_p<PBIT>(Rr, Ri, d0_, c1r_, c1i_)))
#define DIAG_L(PH, RR) DIAG_COEF(PH, RR, (diag_l(Rr, Ri, d0_, c1r_, c1i_)))

#define DISP_COEF(RD, BODY)                                            \
    do {                                                               \
        float r_ = (RD);                                               \
        float p_ = __expf(-0.5f * r_ * r_);                            \
        float m00_ = p_, m01_ = -p_ * r_, m10_ = p_ * r_;              \
        float m11_ = p_ * (1.0f - r_ * r_);                            \
        BODY;                                                          \
    } while (0)

#define ROTDISP_P(PBIT, PH, RD)                                        \
    do {                                                               \
        float sn_, cs_;                                                \
        __sincosf((PH), &sn_, &cs_);                                   \
        rot_p<PBIT>(Rr, Ri, cs_, sn_);                                 \
        DISP_COEF(RD, (disp_p<PBIT>(Rr, Ri, m00_, m01_, m10_, m11_))); \
    } while (0)

#define ROTDISP_L(PH, RD)                                              \
    do {                                                               \
        float sn_, cs_;                                                \
        __sincosf((PH), &sn_, &cs_);                                   \
        rot_l(Rr, Ri, cs_, sn_);                                       \
        DISP_COEF(RD, (disp_l(Rr, Ri, m00_, m01_, m10_, m11_)));       \
    } while (0)

#define ROT_P(PBIT, PH)                                                \
    do {                                                               \
        float sn_, cs_;                                                \
        __sincosf((PH), &sn_, &cs_);                                   \
        rot_p<PBIT>(Rr, Ri, cs_, sn_);                                 \
    } while (0)

#define ROT_L(PH)                                                      \
    do {                                                               \
        float sn_, cs_;                                                \
        __sincosf((PH), &sn_, &cs_);                                   \
        rot_l(Rr, Ri, cs_, sn_);                                       \
    } while (0)

static const int SROW = 66;  // smem row stride (floats): even (float2-aligned), low conflict

__global__ void __launch_bounds__(128)
ffb_kernel(const float* __restrict__ x, const float* __restrict__ var,
           const float* __restrict__ gamma, const float* __restrict__ beta,
           float* __restrict__ out) {
    __shared__ float sm[128 * SROW];

    const int t = threadIdx.x;
    const long long r0 = (long long)blockIdx.x * 128;

    // ---- stage x rows into smem (fully coalesced float4 loads) ----
    {
        const float4* gx = (const float4*)(x + r0 * 64);
#pragma unroll
        for (int k = 0; k < 16; ++k) {
            int g = t + 128 * k;           // float4 index within block tile
            int row = g >> 4, c4 = g & 15;
            float4 v = gx[g];
            float* d = sm + row * SROW + c4 * 4;
            *(float2*)d = f2(v.x, v.y);
            *(float2*)(d + 2) = f2(v.z, v.w);
        }
    }
    __syncthreads();

    const float* xs = sm + t * SROW;  // this thread's row

    float2 Rr[32], Ri[32];

    // ---------------- Encoding collapses to a product state -----------------
    {
        float Ar[6], Brr[6], Bri[6];
#pragma unroll
        for (int w = 0; w < 6; ++w) {
            float r1 = xs[2 * w];
            float e1 = __expf(r1);
            float ch1 = 0.5f * (e1 + __fdividef(1.0f, e1));
            float cw = rsqrtf(ch1);  // sqrt(sech r1)

            float rd = xs[28 + 2 * w];
            float phid = xs[29 + 2 * w];
            float pref = __expf(-0.5f * rd * rd);

            float kk = xs[40 + w];

            float r2 = xs[46 + 2 * w];
            float e2 = __expf(r2);
            float ch2 = 0.5f * (e2 + __fdividef(1.0f, e2));
            float s0 = rsqrtf(ch2);                 // sech^0.5
            float s1 = s0 * __fdividef(1.0f, ch2);  // sech^1.5

            float phr = xs[58 + w];
            float ang = phid + kk + phr;
            float sn, cs;
            __sincosf(ang, &sn, &cs);

            float base = cw * pref;
            Ar[w] = base * s0;
            float bm = base * rd * s1;
            Brr[w] = bm * cs;
            Bri[w] = bm * sn;
        }
        // packed outer product; lane = wire5 bit
        Rr[0] = f2(Ar[5], Brr[5]);
        Ri[0] = f2(0.0f, Bri[5]);
#pragma unroll
        for (int w = 4; w >= 0; --w) {
            const int PL = 1 << (4 - w);
            const float2 vA = bc(Ar[w]), vBr = bc(Brr[w]), vBi = bc(Bri[w]), vnBi = bc(-Bri[w]);
#pragma unroll
            for (int j = 0; j < 16; ++j) {
                if (j < PL) {
                    float2 ar = Rr[j], ai = Ri[j];
                    Rr[PL + j] = fma2(ai, vnBi, mul2(ar, vBr));
                    Ri[PL + j] = fma2(ai, vBr, mul2(ar, vBi));
                    Rr[j] = mul2(ar, vA);
                    Ri[j] = mul2(ai, vA);
                }
            }
        }
    }

    // ---------------- Variational layers ------------------------------------
#pragma unroll 1
    for (int l = 0; l < 2; ++l) {
        const float* v = var + l * 50;

        // BS chain 1: wires (0,1)..(4,5) = amp bits (32,16)..(2,1) = p bits /2
        BS_P(16, 8, V(0), V(1));
        BS_P(8, 4, V(2), V(3));
        BS_P(4, 2, V(4), V(5));
        BS_P(2, 1, V(6), V(7));
        BS_M(V(8), V(9));

        // rot (v[10:16]) fused with squeeze (v[16:22])
        DIAG_P(16, V(10), V(16));
        DIAG_P(8, V(11), V(17));
        DIAG_P(4, V(12), V(18));
        DIAG_P(2, V(13), V(19));
        DIAG_P(1, V(14), V(20));
        DIAG_L(V(15), V(21));

        // BS chain 2 (v[22:32])
        BS_P(16, 8, V(22), V(23));
        BS_P(8, 4, V(24), V(25));
        BS_P(4, 2, V(26), V(27));
        BS_P(2, 1, V(28), V(29));
        BS_M(V(30), V(31));

        // rot (v[32:38]) + real displacement (v[38:44], phi = 0)
        ROTDISP_P(16, V(32), V(38));
        ROTDISP_P(8, V(33), V(39));
        ROTDISP_P(4, V(34), V(40));
        ROTDISP_P(2, V(35), V(41));
        ROTDISP_P(1, V(36), V(42));
        ROTDISP_L(V(37), V(43));

        // Kerr rotations (v[44:50]) — pure phases: skip on last layer
        if (l == 0) {
            ROT_P(16, V(44));
            ROT_P(8, V(45));
            ROT_P(4, V(46));
            ROT_P(2, V(47));
            ROT_P(1, V(48));
            ROT_L(V(49));
        }
    }

    // ---------------- probs + residual + LayerNorm ---------------------------
    float2 acc = f2(0.0f, 0.0f);
#pragma unroll
    for (int p = 0; p < 32; ++p) {
        float2 pr = fma2(Rr[p], Rr[p], mul2(Ri[p], Ri[p]));
        float2 xv = *(const float2*)(xs + 2 * p);
        float2 y = add2(pr, xv);
        Rr[p] = y;  // reuse as y storage
        acc = add2(acc, y);
    }
    float mean = (acc.x + acc.y) * 0.015625f;
    float2 vacc = f2(0.0f, 0.0f);
    const float2 vnm = bc(-mean);
#pragma unroll
    for (int p = 0; p < 32; ++p) {
        float2 d = add2(Rr[p], vnm);
        Rr[p] = d;
        vacc = fma2(d, d, vacc);
    }
    float inv = rsqrtf((vacc.x + vacc.y) * 0.015625f + 1e-5f);
    const float2 vinv = bc(inv);

    float* ys = sm + t * SROW;
    const float2* g2 = (const float2*)gamma;
    const float2* b2 = (const float2*)beta;
#pragma unroll
    for (int p = 0; p < 32; ++p) {
        float2 o = fma2(mul2(Rr[p], vinv), __ldg(g2 + p), __ldg(b2 + p));
        *(float2*)(ys + 2 * p) = o;
    }
    __syncthreads();

    // ---- coalesced float4 stores ----
    {
        float4* go = (float4*)(out + r0 * 64);
#pragma unroll
        for (int k = 0; k < 16; ++k) {
            int g = t + 128 * k;
            int row = g >> 4, c4 = g & 15;
            const float* s = sm + row * SROW + c4 * 4;
            float2 a = *(const float2*)s;
            float2 b = *(const float2*)(s + 2);
            go[g] = make_float4(a.x, a.y, b.x, b.y);
        }
    }
}

extern "C" void kernel_launch(void* const* d_in, const int* in_sizes, int n_in,
                              void* d_out, int out_size) {
    const float* x = (const float*)d_in[0];
    const float* var = (const float*)d_in[1];
    const float* gamma = (const float*)d_in[2];
    const float* beta = (const float*)d_in[3];
    float* out = (float*)d_out;

    int nrows = in_sizes[0] / 64;  // 131072, divisible by 128
    int blocks = nrows / 128;
    ffb_kernel<<<blocks, 128>>>(x, var, gamma, beta, out);
}